// round 15
// baseline (speedup 1.0000x reference)
#include <cuda_runtime.h>
#include <cstdint>
#include <cstddef>

#define BATCH 16
#define CIN   128
#define HI    128
#define WIN   128
#define HO    64
#define WO    64

// ---------------- scratch (device globals; no allocation) ----------------
__device__ float  g_pooled[BATCH * CIN * HO * WO];  // 33.5 MB (skip path)
__device__ uint4  g_xpack[2 * BATCH * HO * WO];     // 2 branches x 128-bit/pixel
__device__ uint4  g_wpack[2 * 128 * 9];             // [br][oc][tap] sign bits
__device__ int    g_corr [2 * 9 * 128];             // [br][class][oc] 1152 + pad correction
__device__ float4 g_ps4[2 * 128];                   // [br][oc] {scale, pb0, alpha, pb1}

// ---------------- constant-memory mirrors (warp-uniform access -> LDC) ----------------
__constant__ uint4  c_wpack[2 * 128 * 9];           // 36864 B
__constant__ float4 c_ps4[2 * 128];                 //  4096 B

// ---------------- CSA helpers (single LOP3 each) ----------------
__device__ __forceinline__ unsigned fa_s(unsigned a, unsigned b, unsigned c) {
    return a ^ b ^ c;
}
__device__ __forceinline__ unsigned fa_c(unsigned a, unsigned b, unsigned c) {
    return (a & b) | (c & (a | b));
}

// ---------------- kernel 1: fused pool+pack (z<16) / weight prep (z==16) ----------------
__global__ void poolpack_kernel(const float* __restrict__ x,
                                const float* __restrict__ mvk1, const float* __restrict__ mvb1,
                                const float* __restrict__ mvk2, const float* __restrict__ mvb2,
                                const float* __restrict__ W1, const float* __restrict__ W2,
                                const float* __restrict__ pb0_1, const float* __restrict__ alpha1,
                                const float* __restrict__ pb1_1, const float* __restrict__ pb0_2,
                                const float* __restrict__ alpha2, const float* __restrict__ pb1_2) {
    int tx = threadIdx.x, ty = threadIdx.y;
    int tid = ty * 32 + tx;

    if (blockIdx.z == 16) {
        // ---- weight prep: half-block = one (br, o); 128 threads = input channels
        __shared__ float red[2][128];
        __shared__ __align__(16) unsigned wb[2][9][4];
        __shared__ int wsum_sm[2][9];
        int half = tid >> 7;
        int i = tid & 127;
        int unit = (blockIdx.x * 64 + blockIdx.y) * 2 + half;
        int br = unit >> 7, o = unit & 127;
        const float* W = br ? W2 : W1;

        float w[9];
        float asum = 0.f;
#pragma unroll
        for (int t = 0; t < 9; ++t) {
            w[t] = W[(o * 128 + i) * 9 + t];
            asum += fabsf(w[t]);
        }
        red[half][i] = asum;
        __syncthreads();
        for (int s = 64; s > 0; s >>= 1) {
            if (i < s) red[half][i] += red[half][i + s];
            __syncthreads();
        }
        int lane = i & 31, wsub = i >> 5;
#pragma unroll
        for (int t = 0; t < 9; ++t) {
            unsigned m = __ballot_sync(0xffffffffu, w[t] > 0.f);
            if (lane == 0) wb[half][t][wsub] = m;
        }
        __syncthreads();
        if (i < 9) {
            uint4 v = *reinterpret_cast<uint4*>(wb[half][i]);
            g_wpack[(br * 128 + o) * 9 + i] = v;
            int ones = __popc(v.x) + __popc(v.y) + __popc(v.z) + __popc(v.w);
            wsum_sm[half][i] = 2 * ones - 128;
        }
        __syncthreads();
        if (i < 9) {                              // border class: yt*3+xt
            int yt = i / 3, xt = i % 3;
            int corr = 1152;                      // constant folded in
#pragma unroll
            for (int t = 0; t < 9; ++t) {
                int tyy = t / 3, txx = t % 3;
                bool pad = (yt == 0 && tyy == 0) || (yt == 2 && tyy == 2) ||
                           (xt == 0 && txx == 0) || (xt == 2 && txx == 2);
                if (pad) corr += wsum_sm[half][t];
            }
            g_corr[(br * 9 + i) * 128 + o] = corr;
        }
        if (i == 0) {
            float4 p;
            p.x = red[half][0] * (1.0f / 1152.0f);
            p.y = br ? pb0_2[o]  : pb0_1[o];
            p.z = br ? alpha2[o] : alpha1[o];
            p.w = br ? pb1_2[o]  : pb1_1[o];
            g_ps4[br * 128 + o] = p;
        }
        return;
    }

    // ---- pool + binarize + bit-pack
    __shared__ unsigned words[2][32][4];
    reinterpret_cast<unsigned*>(words)[tid] = 0u;
    __syncthreads();

    int b = blockIdx.z, y = blockIdx.y, x0 = blockIdx.x * 32;
    int xo = x0 + tx;
    const float2* p = reinterpret_cast<const float2*>(x);

    unsigned acc1 = 0, acc2 = 0;
#pragma unroll
    for (int i = 0; i < 16; ++i) {
        int c = ty * 16 + i;                                  // warp-uniform channel
        int base = ((b * CIN + c) * HI + 2 * y) * (WIN / 2) + xo;
        float2 r0 = p[base];
        float2 r1 = p[base + WIN / 2];
        float v = 0.25f * ((r0.x + r0.y) + (r1.x + r1.y));
        g_pooled[((b * CIN + c) * HO + y) * WO + xo] = v;
        unsigned bit = 1u << ((ty & 1) * 16 + i);             // c & 31
        if (v * mvk1[c] + mvb1[c] > 0.f) acc1 |= bit;
        if (v * mvk2[c] + mvb2[c] > 0.f) acc2 |= bit;
    }
    atomicOr(&words[0][tx][ty >> 1], acc1);
    atomicOr(&words[1][tx][ty >> 1], acc2);
    __syncthreads();

    int br = tid >> 7;
    int rem = tid & 127;
    int px = rem >> 2, w = rem & 3;
    reinterpret_cast<unsigned*>(g_xpack)[(((br * BATCH + b) * HO + y) * WO + x0 + px) * 4 + w] =
        words[br][px][w];
}

// ---------------- miss count: balanced CSA (18 FA) + 18 POPC ----------------
// weights read from __constant__ (warp-uniform index -> LDC broadcast)
__device__ __forceinline__ int csa_miss(const uint4 in[9], int wbase) {
    unsigned v[36];
#pragma unroll
    for (int t = 0; t < 9; ++t) {
        uint4 w = c_wpack[wbase + t];
        v[4 * t + 0] = in[t].x ^ w.x;
        v[4 * t + 1] = in[t].y ^ w.y;
        v[4 * t + 2] = in[t].z ^ w.z;
        v[4 * t + 3] = in[t].w ^ w.w;
    }
    unsigned s1[12], c1[12];
#pragma unroll
    for (int g = 0; g < 3; ++g)
#pragma unroll
        for (int k = 0; k < 4; ++k) {
            unsigned a = v[12 * g + k], b = v[12 * g + 4 + k], c = v[12 * g + 8 + k];
            s1[g * 4 + k] = fa_s(a, b, c);
            c1[g * 4 + k] = fa_c(a, b, c);
        }
    unsigned s2[4], c2[4];
#pragma unroll
    for (int k = 0; k < 4; ++k) {
        s2[k] = fa_s(s1[k], s1[4 + k], s1[8 + k]);
        c2[k] = fa_c(s1[k], s1[4 + k], s1[8 + k]);
    }
    unsigned d0 = fa_s(c1[0], c1[1], c1[2]), e0 = fa_c(c1[0], c1[1], c1[2]);
    unsigned d1 = fa_s(c1[3], c1[4], c1[5]), e1 = fa_c(c1[3], c1[4], c1[5]);

    int m1 = __popc(s2[0]) + __popc(s2[1]) + __popc(s2[2]) + __popc(s2[3]);
    int m2 = __popc(d0) + __popc(d1)
           + __popc(c1[6]) + __popc(c1[7]) + __popc(c1[8])
           + __popc(c1[9]) + __popc(c1[10]) + __popc(c1[11])
           + __popc(c2[0]) + __popc(c2[1]) + __popc(c2[2]) + __popc(c2[3]);
    int m4 = __popc(e0) + __popc(e1);
    return m1 + 2 * m2 + 4 * m4;
}

// ---------------- kernel 2: XNOR-CSA-popcount conv + RPReLU + skip + concat ----------------
// grid (8,16,32); z = b*2+br; block tile = 32 px (8x4) x 128 oc; 256 threads
// thread = 1 pixel (lane) x 16 oc; weights/params in __constant__ (no per-block fill)
__global__ __launch_bounds__(256, 3) void conv_kernel(float* __restrict__ out) {
    __shared__ int   corr_s[9 * 128];        //  4608 B  [class][oc] (lane-divergent index)
    __shared__ uint4 tile[60];               //   960 B  (6x10 halo)

    int tid = threadIdx.x, wid = tid >> 5, lane = tid & 31;
    int z = blockIdx.z;
    int b = z >> 1, br = z & 1;
    int ty = blockIdx.y, tx = blockIdx.x;    // y-tile 0..15 (4 rows), x-tile 0..7 (8 cols)

    for (int k = tid; k < 1152; k += 256) corr_s[k] = g_corr[br * 1152 + k];
    if (tid < 60) {
        int r = tid / 10, cc = tid % 10;
        int gy = ty * 4 - 1 + r, gx = tx * 8 - 1 + cc;
        uint4 v = make_uint4(0, 0, 0, 0);
        if (gy >= 0 && gy < 64 && gx >= 0 && gx < 64)
            v = g_xpack[((br * BATCH + b) * HO + gy) * WO + gx];
        tile[tid] = v;
    }
    __syncthreads();

    int py = lane >> 3, px = lane & 7;
    int gy = ty * 4 + py, gx = tx * 8 + px;

    uint4 in[9];
#pragma unroll
    for (int t = 0; t < 9; ++t) {
        int dy = t / 3 - 1, dx = t % 3 - 1;
        in[t] = tile[(py + 1 + dy) * 10 + (px + 1 + dx)];
    }

    // border class: (top/mid/bot)*3 + (left/mid/right)
    int cls = ((gy == 0) ? 0 : (gy == 63) ? 2 : 1) * 3 + ((gx == 0) ? 0 : (gx == 63) ? 2 : 1);
    int cbase = cls * 128;

    const float* pooled_p = &g_pooled[(b * CIN * HO + gy) * WO + gx];
    float* out_p = &out[((b * 256 + br * 128) * HO + gy) * WO + gx];

#pragma unroll
    for (int jg = 0; jg < 4; ++jg) {
        int o0 = (wid << 4) + jg * 4;
        // batched skip-path prefetch: 4 LDGs in flight while CSA math runs
        float pv[4];
#pragma unroll
        for (int u = 0; u < 4; ++u)
            pv[u] = pooled_p[(o0 + u) * (HO * WO)];
#pragma unroll
        for (int u = 0; u < 4; ++u) {
            int o = o0 + u;                  // warp-uniform
            int miss = csa_miss(in, br * 1152 + o * 9);
            float4 pp = c_ps4[br * 128 + o];
            int S = corr_s[cbase + o] - 2 * miss;
            float yv = fmaf(pp.x, (float)S, pp.y);
            yv = (yv >= 0.f) ? yv : pp.z * yv;
            yv += pp.w;
            out_p[o * (HO * WO)] = pv[u] + yv;
        }
    }
}

// ---------------- launch ----------------
extern "C" void kernel_launch(void* const* d_in, const int* in_sizes, int n_in,
                              void* d_out, int out_size) {
    const float* x      = (const float*)d_in[0];
    const float* W1     = (const float*)d_in[1];
    const float* mvk1   = (const float*)d_in[2];
    const float* mvb1   = (const float*)d_in[3];
    // d_in[4] = beta1 (forward value is sign(); beta only affects gradients)
    const float* pb0_1  = (const float*)d_in[5];
    const float* alpha1 = (const float*)d_in[6];
    const float* pb1_1  = (const float*)d_in[7];
    const float* W2     = (const float*)d_in[8];
    const float* mvk2   = (const float*)d_in[9];
    const float* mvb2   = (const float*)d_in[10];
    // d_in[11] = beta2
    const float* pb0_2  = (const float*)d_in[12];
    const float* alpha2 = (const float*)d_in[13];
    const float* pb1_2  = (const float*)d_in[14];
    float* out = (float*)d_out;

    poolpack_kernel<<<dim3(2, 64, 17), dim3(32, 8)>>>(x, mvk1, mvb1, mvk2, mvb2,
                                                      W1, W2, pb0_1, alpha1, pb1_1,
                                                      pb0_2, alpha2, pb1_2);

    // mirror weight/param tables into __constant__ (device-to-device, graph-capturable)
    void* wsrc = nullptr;
    void* psrc = nullptr;
    cudaGetSymbolAddress(&wsrc, g_wpack);
    cudaGetSymbolAddress(&psrc, g_ps4);
    cudaMemcpyToSymbolAsync(c_wpack, wsrc, sizeof(uint4) * 2 * 128 * 9, 0,
                            cudaMemcpyDeviceToDevice, 0);
    cudaMemcpyToSymbolAsync(c_ps4, psrc, sizeof(float4) * 2 * 128, 0,
                            cudaMemcpyDeviceToDevice, 0);

    conv_kernel<<<dim3(8, 16, BATCH * 2), 256>>>(out);
}

// round 16
// speedup vs baseline: 3.8815x; 3.8815x over previous
#include <cuda_runtime.h>
#include <cstdint>
#include <cstddef>

#define BATCH 16
#define CIN   128
#define HI    128
#define WIN   128
#define HO    64
#define WO    64

// ---------------- scratch (device globals; no allocation) ----------------
__device__ float  g_pooled[BATCH * CIN * HO * WO];  // 33.5 MB (skip path)
__device__ uint4  g_xpack[2 * BATCH * HO * WO];     // 2 branches x 128-bit/pixel
__device__ uint4  g_wpack[2 * 128 * 9];             // [br][oc][tap] sign bits
__device__ int    g_corr [2 * 9 * 128];             // [br][class][oc] 1152 + pad correction
__device__ float4 g_ps4[2 * 128];                   // [br][oc] {scale, pb0, alpha, pb1}

// ---------------- CSA helpers (single LOP3 each) ----------------
__device__ __forceinline__ unsigned fa_s(unsigned a, unsigned b, unsigned c) {
    return a ^ b ^ c;
}
__device__ __forceinline__ unsigned fa_c(unsigned a, unsigned b, unsigned c) {
    return (a & b) | (c & (a | b));
}

// ---------------- kernel 1: fused pool+pack (z<16) / weight prep (z==16) ----------------
__global__ void poolpack_kernel(const float* __restrict__ x,
                                const float* __restrict__ mvk1, const float* __restrict__ mvb1,
                                const float* __restrict__ mvk2, const float* __restrict__ mvb2,
                                const float* __restrict__ W1, const float* __restrict__ W2,
                                const float* __restrict__ pb0_1, const float* __restrict__ alpha1,
                                const float* __restrict__ pb1_1, const float* __restrict__ pb0_2,
                                const float* __restrict__ alpha2, const float* __restrict__ pb1_2) {
    int tx = threadIdx.x, ty = threadIdx.y;
    int tid = ty * 32 + tx;

    if (blockIdx.z == 16) {
        // ---- weight prep: half-block = one (br, o); 128 threads = input channels
        __shared__ float red[2][128];
        __shared__ __align__(16) unsigned wb[2][9][4];
        __shared__ int wsum_sm[2][9];
        int half = tid >> 7;
        int i = tid & 127;
        int unit = (blockIdx.x * 64 + blockIdx.y) * 2 + half;
        int br = unit >> 7, o = unit & 127;
        const float* W = br ? W2 : W1;

        float w[9];
        float asum = 0.f;
#pragma unroll
        for (int t = 0; t < 9; ++t) {
            w[t] = W[(o * 128 + i) * 9 + t];
            asum += fabsf(w[t]);
        }
        red[half][i] = asum;
        __syncthreads();
        for (int s = 64; s > 0; s >>= 1) {
            if (i < s) red[half][i] += red[half][i + s];
            __syncthreads();
        }
        int lane = i & 31, wsub = i >> 5;
#pragma unroll
        for (int t = 0; t < 9; ++t) {
            unsigned m = __ballot_sync(0xffffffffu, w[t] > 0.f);
            if (lane == 0) wb[half][t][wsub] = m;
        }
        __syncthreads();
        if (i < 9) {
            uint4 v = *reinterpret_cast<uint4*>(wb[half][i]);
            g_wpack[(br * 128 + o) * 9 + i] = v;
            int ones = __popc(v.x) + __popc(v.y) + __popc(v.z) + __popc(v.w);
            wsum_sm[half][i] = 2 * ones - 128;
        }
        __syncthreads();
        if (i < 9) {                              // border class: yt*3+xt
            int yt = i / 3, xt = i % 3;
            int corr = 1152;                      // constant folded in
#pragma unroll
            for (int t = 0; t < 9; ++t) {
                int tyy = t / 3, txx = t % 3;
                bool pad = (yt == 0 && tyy == 0) || (yt == 2 && tyy == 2) ||
                           (xt == 0 && txx == 0) || (xt == 2 && txx == 2);
                if (pad) corr += wsum_sm[half][t];
            }
            g_corr[(br * 9 + i) * 128 + o] = corr;
        }
        if (i == 0) {
            float4 p;
            p.x = red[half][0] * (1.0f / 1152.0f);
            p.y = br ? pb0_2[o]  : pb0_1[o];
            p.z = br ? alpha2[o] : alpha1[o];
            p.w = br ? pb1_2[o]  : pb1_1[o];
            g_ps4[br * 128 + o] = p;
        }
        return;
    }

    // ---- pool + binarize + bit-pack
    __shared__ unsigned words[2][32][4];
    reinterpret_cast<unsigned*>(words)[tid] = 0u;
    __syncthreads();

    int b = blockIdx.z, y = blockIdx.y, x0 = blockIdx.x * 32;
    int xo = x0 + tx;
    const float2* p = reinterpret_cast<const float2*>(x);

    unsigned acc1 = 0, acc2 = 0;
#pragma unroll
    for (int i = 0; i < 16; ++i) {
        int c = ty * 16 + i;                                  // warp-uniform channel
        int base = ((b * CIN + c) * HI + 2 * y) * (WIN / 2) + xo;
        float2 r0 = p[base];
        float2 r1 = p[base + WIN / 2];
        float v = 0.25f * ((r0.x + r0.y) + (r1.x + r1.y));
        g_pooled[((b * CIN + c) * HO + y) * WO + xo] = v;
        unsigned bit = 1u << ((ty & 1) * 16 + i);             // c & 31
        if (v * mvk1[c] + mvb1[c] > 0.f) acc1 |= bit;
        if (v * mvk2[c] + mvb2[c] > 0.f) acc2 |= bit;
    }
    atomicOr(&words[0][tx][ty >> 1], acc1);
    atomicOr(&words[1][tx][ty >> 1], acc2);
    __syncthreads();

    int br = tid >> 7;
    int rem = tid & 127;
    int px = rem >> 2, w = rem & 3;
    reinterpret_cast<unsigned*>(g_xpack)[(((br * BATCH + b) * HO + y) * WO + x0 + px) * 4 + w] =
        words[br][px][w];
}

// ---------------- miss count: balanced CSA (18 FA) + 18 POPC ----------------
__device__ __forceinline__ int csa_miss(const uint4 in[9], const uint4* __restrict__ wp) {
    unsigned v[36];
#pragma unroll
    for (int t = 0; t < 9; ++t) {
        uint4 w = wp[t];
        v[4 * t + 0] = in[t].x ^ w.x;
        v[4 * t + 1] = in[t].y ^ w.y;
        v[4 * t + 2] = in[t].z ^ w.z;
        v[4 * t + 3] = in[t].w ^ w.w;
    }
    unsigned s1[12], c1[12];
#pragma unroll
    for (int g = 0; g < 3; ++g)
#pragma unroll
        for (int k = 0; k < 4; ++k) {
            unsigned a = v[12 * g + k], b = v[12 * g + 4 + k], c = v[12 * g + 8 + k];
            s1[g * 4 + k] = fa_s(a, b, c);
            c1[g * 4 + k] = fa_c(a, b, c);
        }
    unsigned s2[4], c2[4];
#pragma unroll
    for (int k = 0; k < 4; ++k) {
        s2[k] = fa_s(s1[k], s1[4 + k], s1[8 + k]);
        c2[k] = fa_c(s1[k], s1[4 + k], s1[8 + k]);
    }
    unsigned d0 = fa_s(c1[0], c1[1], c1[2]), e0 = fa_c(c1[0], c1[1], c1[2]);
    unsigned d1 = fa_s(c1[3], c1[4], c1[5]), e1 = fa_c(c1[3], c1[4], c1[5]);

    int m1 = __popc(s2[0]) + __popc(s2[1]) + __popc(s2[2]) + __popc(s2[3]);
    int m2 = __popc(d0) + __popc(d1)
           + __popc(c1[6]) + __popc(c1[7]) + __popc(c1[8])
           + __popc(c1[9]) + __popc(c1[10]) + __popc(c1[11])
           + __popc(c2[0]) + __popc(c2[1]) + __popc(c2[2]) + __popc(c2[3]);
    int m4 = __popc(e0) + __popc(e1);
    return m1 + 2 * m2 + 4 * m4;
}

// ---------------- kernel 2: XNOR-CSA-popcount conv + RPReLU + skip + concat ----------------
// grid (4,32,32); z = b*2+br; block tile = 32 px (16 cols x 2 rows) x 128 oc; 256 threads
// thread = 1 pixel (lane = row*16+col) x 16 oc; stores coalesce as 2x64B per (oc, warp)
__global__ __launch_bounds__(256, 3) void conv_kernel(float* __restrict__ out) {
    __shared__ uint4  w_s[128 * 9];          // 18432 B  [oc][tap]
    __shared__ int    corr_s[9 * 128];       //  4608 B  [class][oc], includes +1152
    __shared__ float4 ps4[128];              //  2048 B
    __shared__ uint4  tile[72];              //  1152 B  (4x18 halo)

    int tid = threadIdx.x, wid = tid >> 5, lane = tid & 31;
    int z = blockIdx.z;
    int b = z >> 1, br = z & 1;
    int ty = blockIdx.y, tx = blockIdx.x;    // y-tile 0..31 (2 rows), x-tile 0..3 (16 cols)

    for (int k = tid; k < 1152; k += 256) {
        w_s[k] = g_wpack[br * 1152 + k];
        corr_s[k] = g_corr[br * 1152 + k];
    }
    if (tid < 128) ps4[tid] = g_ps4[br * 128 + tid];
    if (tid < 72) {
        int r = tid / 18, cc = tid % 18;
        int gy = ty * 2 - 1 + r, gx = tx * 16 - 1 + cc;
        uint4 v = make_uint4(0, 0, 0, 0);
        if (gy >= 0 && gy < 64 && gx >= 0 && gx < 64)
            v = g_xpack[((br * BATCH + b) * HO + gy) * WO + gx];
        tile[tid] = v;
    }
    __syncthreads();

    int py = lane >> 4, px = lane & 15;      // 2 rows x 16 cols
    int gy = ty * 2 + py, gx = tx * 16 + px;

    uint4 in[9];
#pragma unroll
    for (int t = 0; t < 9; ++t) {
        int dy = t / 3 - 1, dx = t % 3 - 1;
        in[t] = tile[(py + 1 + dy) * 18 + (px + 1 + dx)];
    }

    // border class: (top/mid/bot)*3 + (left/mid/right); interior blocks are all class 4
    bool interior = (ty > 0) && (ty < 31) && (tx > 0) && (tx < 3);
    int cls = ((gy == 0) ? 0 : (gy == 63) ? 2 : 1) * 3 + ((gx == 0) ? 0 : (gx == 63) ? 2 : 1);
    int cbase = cls * 128;

    const float* pooled_p = &g_pooled[(b * CIN * HO + gy) * WO + gx];
    float* out_p = &out[((b * 256 + br * 128) * HO + gy) * WO + gx];

#pragma unroll
    for (int jg = 0; jg < 4; ++jg) {
        int o0 = (wid << 4) + jg * 4;
        // batched skip-path prefetch: 4 LDGs in flight while CSA math runs
        float pv[4];
#pragma unroll
        for (int u = 0; u < 4; ++u)
            pv[u] = pooled_p[(o0 + u) * (HO * WO)];
#pragma unroll
        for (int u = 0; u < 4; ++u) {
            int o = o0 + u;                  // warp-uniform -> LDS broadcast
            int miss = csa_miss(in, &w_s[o * 9]);
            float4 pp = ps4[o];
            int cv = interior ? 1152 : corr_s[cbase + o];
            int S = cv - 2 * miss;
            float yv = fmaf(pp.x, (float)S, pp.y);
            yv = (yv >= 0.f) ? yv : pp.z * yv;
            yv += pp.w;
            out_p[o * (HO * WO)] = pv[u] + yv;
        }
    }
}

// ---------------- launch ----------------
extern "C" void kernel_launch(void* const* d_in, const int* in_sizes, int n_in,
                              void* d_out, int out_size) {
    const float* x      = (const float*)d_in[0];
    const float* W1     = (const float*)d_in[1];
    const float* mvk1   = (const float*)d_in[2];
    const float* mvb1   = (const float*)d_in[3];
    // d_in[4] = beta1 (forward value is sign(); beta only affects gradients)
    const float* pb0_1  = (const float*)d_in[5];
    const float* alpha1 = (const float*)d_in[6];
    const float* pb1_1  = (const float*)d_in[7];
    const float* W2     = (const float*)d_in[8];
    const float* mvk2   = (const float*)d_in[9];
    const float* mvb2   = (const float*)d_in[10];
    // d_in[11] = beta2
    const float* pb0_2  = (const float*)d_in[12];
    const float* alpha2 = (const float*)d_in[13];
    const float* pb1_2  = (const float*)d_in[14];
    float* out = (float*)d_out;

    poolpack_kernel<<<dim3(2, 64, 17), dim3(32, 8)>>>(x, mvk1, mvb1, mvk2, mvb2,
                                                      W1, W2, pb0_1, alpha1, pb1_1,
                                                      pb0_2, alpha2, pb1_2);
    conv_kernel<<<dim3(4, 32, BATCH * 2), 256>>>(out);
}